// round 7
// baseline (speedup 1.0000x reference)
#include <cuda_runtime.h>
#include <math.h>

typedef unsigned long long u64;
typedef unsigned int u32;

#define Nn 100000
#define Ee 1600000
#define Ff 128
#define NFf 4
#define Dd 64
#define NLl 3
#define Gg 128
#define NTILE 782   // ceil(Nn/128)

// ---------------- device scratch (no allocations allowed) ----------------
__device__ int   g_deg[Nn];
__device__ int   g_rowptr[Nn + 1];
__device__ int   g_fill[Nn];
__device__ int   g_bsums[256];
__device__ int   g_srcs[Ee];
__device__ int   g_eids[Ee];
__device__ float g_wcsr[NFf * Ee];
__device__ float g_stateA[NFf * Nn * Dd];
__device__ float g_stateB[NFf * Nn * Dd];
__device__ int   g_gcnt[Gg];
__device__ int   g_gstart[Gg + 1];
__device__ float g_packcv[NFf * NLl * 8192];   // [wl][k][lane] f4: wrel0,wrel1,wroot0,wroot1
__device__ float g_packrzi[NFf * 8192];        // [f][k][lane] f4: wih_r0,wih_r1,wih_z0,wih_z1
__device__ float g_packrzh[NFf * 8192];        // [f][k][lane] f4: whh_r0,whh_r1,whh_z0,whh_z1
__device__ float g_packn[NFf * 8192];          // [f][k][lane] f4: wih_n0,wih_n1,whh_n0,whh_n1

// ---------------- packed f32x2 helpers ----------------
__device__ __forceinline__ u64 ffma2(u64 a, u64 b, u64 c) {
    u64 d; asm("fma.rn.f32x2 %0,%1,%2,%3;" : "=l"(d) : "l"(a), "l"(b), "l"(c)); return d;
}
__device__ __forceinline__ u64 splat2(float v) {
    u64 d; u32 r = __float_as_uint(v);
    asm("mov.b64 %0,{%1,%2};" : "=l"(d) : "r"(r), "r"(r)); return d;
}
__device__ __forceinline__ float2 unpk(u64 v) {
    u32 lo, hi; asm("mov.b64 {%0,%1},%2;" : "=r"(lo), "=r"(hi) : "l"(v));
    return make_float2(__uint_as_float(lo), __uint_as_float(hi));
}
__device__ __forceinline__ u64 pk(float a, float b) {
    u64 d;
    asm("mov.b64 %0,{%1,%2};" : "=l"(d) : "r"(__float_as_uint(a)), "r"(__float_as_uint(b)));
    return d;
}
__device__ __forceinline__ float sigm(float v) { return 1.f / (1.f + __expf(-v)); }
__device__ __forceinline__ float tanh_f(float v) { return 2.f / (1.f + __expf(-2.f * v)) - 1.f; }

// load 4 node-pair u64s (32B) via 2 LDS.128 — no packing MOVs
#define LOADU2(dst, base) do { \
    const ulonglong2* _p = (const ulonglong2*)(base); \
    ulonglong2 _a = _p[0], _b = _p[1]; \
    dst[0] = _a.x; dst[1] = _a.y; dst[2] = _b.x; dst[3] = _b.y; \
} while (0)

// ---------------- CSR build ----------------
__global__ void k_zero() {
    int i = blockIdx.x * blockDim.x + threadIdx.x;
    if (i < Nn) g_deg[i] = 0;
    if (i < Gg) g_gcnt[i] = 0;
}

__global__ void k_hist(const int* __restrict__ dst, const int* __restrict__ batch) {
    int i = blockIdx.x * blockDim.x + threadIdx.x;
    if (i < Ee) atomicAdd(&g_deg[dst[i]], 1);
    if (i < Nn) atomicAdd(&g_gcnt[batch[i]], 1);
}

__global__ void k_scan1() {
    __shared__ int tmp[1024];
    int i = blockIdx.x * 1024 + threadIdx.x;
    int v = (i < Nn) ? g_deg[i] : 0;
    tmp[threadIdx.x] = v;
    __syncthreads();
    for (int off = 1; off < 1024; off <<= 1) {
        int t = 0;
        if (threadIdx.x >= off) t = tmp[threadIdx.x - off];
        __syncthreads();
        if (threadIdx.x >= off) tmp[threadIdx.x] += t;
        __syncthreads();
    }
    if (i < Nn) g_rowptr[i + 1] = tmp[threadIdx.x];
    if (threadIdx.x == 1023) g_bsums[blockIdx.x] = tmp[1023];
}

__global__ void k_scan2(int nb) {
    if (threadIdx.x == 0 && blockIdx.x == 0) {
        int run = 0;
        for (int b = 0; b < nb; b++) { int v = g_bsums[b]; g_bsums[b] = run; run += v; }
    }
}

__global__ void k_scan3() {
    int i = blockIdx.x * 1024 + threadIdx.x;
    if (i < Nn) {
        int v = g_rowptr[i + 1] + g_bsums[blockIdx.x];
        g_rowptr[i + 1] = v;
        if (i + 1 < Nn) g_fill[i + 1] = v;
    }
    if (i == 0) { g_rowptr[0] = 0; g_fill[0] = 0; }
}

__global__ void k_scatter(const int* __restrict__ src, const int* __restrict__ dst) {
    int e = blockIdx.x * blockDim.x + threadIdx.x;
    if (e < Ee) {
        int d = dst[e];
        int p = atomicAdd(&g_fill[d], 1);
        g_srcs[p] = src[e];
        g_eids[p] = e;
    }
}

__global__ void k_sortseg() {
    int n = blockIdx.x * blockDim.x + threadIdx.x;
    if (n >= Nn) return;
    int b = g_rowptr[n], e = g_rowptr[n + 1];
    for (int i = b + 1; i < e; i++) {
        int ke = g_eids[i], ks = g_srcs[i];
        int j = i - 1;
        while (j >= b && g_eids[j] > ke) {
            g_eids[j + 1] = g_eids[j];
            g_srcs[j + 1] = g_srcs[j];
            j--;
        }
        g_eids[j + 1] = ke;
        g_srcs[j + 1] = ks;
    }
}

__global__ void k_buildw(const float* __restrict__ att) {
    int j = blockIdx.x * blockDim.x + threadIdx.x;
    if (j < Ee) {
        int e = g_eids[j];
#pragma unroll
        for (int f = 0; f < NFf; f++) g_wcsr[f * Ee + j] = att[f * Ee + e];
    }
}

__global__ void k_gscan() {
    if (threadIdx.x == 0 && blockIdx.x == 0) {
        int run = 0;
        for (int g = 0; g < Gg; g++) { g_gstart[g] = run; run += g_gcnt[g]; }
        g_gstart[Gg] = run;
    }
}

// ---------------- weight pre-pack ----------------
__global__ void k_pack(const float* __restrict__ Wrel, const float* __restrict__ Wroot,
                       const float* __restrict__ Wih, const float* __restrict__ Whh) {
    int i = blockIdx.x * blockDim.x + threadIdx.x;
    if (i < 24576) {           // conv: 12 layers x 2048
        int wl = i >> 11, r = i & 2047, k = r >> 5, l = r & 31;
        const float* A = Wrel + wl * 4096;
        const float* B = Wroot + wl * 4096;
        ((float4*)g_packcv)[i] = make_float4(A[k * 64 + 2 * l], A[k * 64 + 2 * l + 1],
                                             B[k * 64 + 2 * l], B[k * 64 + 2 * l + 1]);
        return;
    }
    int j = i - 24576;
    if (j < 8192) {            // rz input weights
        int f = j >> 11, r = j & 2047, k = r >> 5, l = r & 31;
        const float* I = Wih + f * 12288;
        ((float4*)g_packrzi)[j] = make_float4(I[(2 * l) * 64 + k], I[(2 * l + 1) * 64 + k],
                                              I[(64 + 2 * l) * 64 + k], I[(64 + 2 * l + 1) * 64 + k]);
        return;
    }
    j -= 8192;
    if (j < 8192) {            // rz hidden weights
        int f = j >> 11, r = j & 2047, k = r >> 5, l = r & 31;
        const float* H = Whh + f * 12288;
        ((float4*)g_packrzh)[j] = make_float4(H[(2 * l) * 64 + k], H[(2 * l + 1) * 64 + k],
                                              H[(64 + 2 * l) * 64 + k], H[(64 + 2 * l + 1) * 64 + k]);
        return;
    }
    j -= 8192;
    if (j < 8192) {            // n gate weights (ih + hh)
        int f = j >> 11, r = j & 2047, k = r >> 5, l = r & 31;
        const float* I = Wih + f * 12288;
        const float* H = Whh + f * 12288;
        ((float4*)g_packn)[j] = make_float4(I[(128 + 2 * l) * 64 + k], I[(128 + 2 * l + 1) * 64 + k],
                                            H[(128 + 2 * l) * 64 + k], H[(128 + 2 * l + 1) * 64 + k]);
    }
}

// ---------------- lin (all factors, 8 nodes/warp, 16 warps) ----------------
#define LIN_SHM ((8192 + 64 + 16 * 1536) * 4)
__global__ __launch_bounds__(512, 1) void k_lin(const float* __restrict__ x,
                                                const float* __restrict__ W_all,
                                                const float* __restrict__ b_all,
                                                float* __restrict__ out_base) {
    extern __shared__ float sh[];
    float* sW = sh;
    float* sb = sW + 8192;
    float* sX = sb + 64;
    int f = blockIdx.x & 3;
    int fslot = blockIdx.x >> 2;
    int nslot = gridDim.x >> 2;
    const float* W = W_all + f * Ff * Dd;
    const float* b = b_all + f * Dd;
    float* out = out_base + f * Nn * Dd;

    int tid = threadIdx.x;
    for (int i = tid; i < 8192; i += 512) sW[i] = W[i];
    if (tid < 64) sb[tid] = b[tid];
    __syncthreads();
    int warp = tid >> 5, lane = tid & 31;
    int d0 = 2 * lane;
    int nt = lane >> 2, cg = lane & 3;
    float* sXw = sX + warp * 1536;   // [col][12]
    float bc0 = sb[d0], bc1 = sb[d0 + 1];

    for (int t = fslot; t < NTILE; t += nslot) {
        int n0 = t * 128 + warp * 8;
        if (n0 >= Nn) continue;
        {
            int n = n0 + nt;
            bool v = n < Nn;
            const float4* xr = (const float4*)(x + (v ? n : 0) * Ff) + cg * 8;
#pragma unroll
            for (int q = 0; q < 8; q++) {
                float4 tv = v ? xr[q] : make_float4(0, 0, 0, 0);
                int c = cg * 32 + q * 4;
                sXw[(c + 0) * 12 + nt] = tv.x;
                sXw[(c + 1) * 12 + nt] = tv.y;
                sXw[(c + 2) * 12 + nt] = tv.z;
                sXw[(c + 3) * 12 + nt] = tv.w;
            }
        }
        __syncwarp();
        u64 acc[4][2];
#pragma unroll
        for (int p = 0; p < 4; p++) { acc[p][0] = 0ull; acc[p][1] = 0ull; }
#pragma unroll 4
        for (int k = 0; k < Ff; k++) {
            float2 w = *(const float2*)(sW + k * 64 + d0);
            u64 sw0 = splat2(w.x), sw1 = splat2(w.y);
            u64 xv[4];
            LOADU2(xv, sXw + k * 12);
#pragma unroll
            for (int p = 0; p < 4; p++) {
                acc[p][0] = ffma2(xv[p], sw0, acc[p][0]);
                acc[p][1] = ffma2(xv[p], sw1, acc[p][1]);
            }
        }
#pragma unroll
        for (int p = 0; p < 4; p++) {
            float2 a0 = unpk(acc[p][0]), a1 = unpk(acc[p][1]);
            int na = n0 + 2 * p, nb = na + 1;
            if (na < Nn) *(float2*)(out + na * 64 + d0) = make_float2(a0.x + bc0, a1.x + bc1);
            if (nb < Nn) *(float2*)(out + nb * 64 + d0) = make_float2(a0.y + bc0, a1.y + bc1);
        }
        __syncwarp();
    }
}

// ---------------- fused layer (all factors, 8 nodes/warp, 16 warps) ----------------
// stage stride 12 floats (48B, 16B-aligned) so acts load as LDS.128 -> ulonglong2
#define LAYER_SHM ((8192 * 4 + 16 * 1536) * 4)
__global__ __launch_bounds__(512, 1) void k_layer(const float* __restrict__ in_base,
                                                  float* __restrict__ out_base,
                                                  int layer,
                                                  const float* __restrict__ brel_all,
                                                  const float* __restrict__ bih_all,
                                                  const float* __restrict__ bhh_all) {
    extern __shared__ float sh[];
    float* sWcv  = sh;               // 8192: [k][lane] f4
    float* sWrzi = sWcv + 8192;      // 8192
    float* sWrzh = sWrzi + 8192;     // 8192
    float* sWn   = sWrzh + 8192;     // 8192
    float* sStage = sWn + 8192;      // 16 warps * 1536

    int f = blockIdx.x & 3;
    int fslot = blockIdx.x >> 2;
    int nslot = gridDim.x >> 2;
    int wl = f * NLl + layer;
    const float* in_state = in_base + f * Nn * Dd;
    float* out_state = out_base + f * Nn * Dd;
    const float* wfp = g_wcsr + f * Ee;

    int tid = threadIdx.x;
    {
        const float4* p0 = (const float4*)(g_packcv + wl * 8192);
        const float4* p1 = (const float4*)(g_packrzi + f * 8192);
        const float4* p2 = (const float4*)(g_packrzh + f * 8192);
        const float4* p3 = (const float4*)(g_packn + f * 8192);
        float4* d0_ = (float4*)sWcv;
        float4* d1_ = (float4*)sWrzi;
        float4* d2_ = (float4*)sWrzh;
        float4* d3_ = (float4*)sWn;
        for (int i = tid; i < 2048; i += 512) {
            d0_[i] = p0[i]; d1_[i] = p1[i]; d2_[i] = p2[i]; d3_[i] = p3[i];
        }
    }
    __syncthreads();

    int warp = tid >> 5, lane = tid & 31;
    int d0 = 2 * lane;
    int nt = lane >> 2, cg = lane & 3;
    float* sIn = sStage + warp * 1536;   // [col][12]
    float* sA  = sIn + 768;              // agg, then m

    const float* brel = brel_all + wl * 64;
    float br0 = brel[d0], br1 = brel[d0 + 1];
    float bi_[6], bh_[6];
#pragma unroll
    for (int g = 0; g < 3; g++) {
        bi_[2 * g] = bih_all[f * 192 + 64 * g + d0];
        bi_[2 * g + 1] = bih_all[f * 192 + 64 * g + d0 + 1];
        bh_[2 * g] = bhh_all[f * 192 + 64 * g + d0];
        bh_[2 * g + 1] = bhh_all[f * 192 + 64 * g + d0 + 1];
    }

    for (int t = fslot; t < NTILE; t += nslot) {
        int n0 = t * 128 + warp * 8;
        if (n0 >= Nn) continue;

        // ---- stage h + edge aggregation, transposed [col][node] ----
        {
            int n = n0 + nt;
            bool v = n < Nn;
            const float4* xr = (const float4*)(in_state + (v ? n : 0) * 64) + cg * 4;
            float acc16[16];
#pragma unroll
            for (int q = 0; q < 4; q++) {
                float4 tv = v ? xr[q] : make_float4(0, 0, 0, 0);
                int c = cg * 16 + q * 4;
                sIn[(c + 0) * 12 + nt] = tv.x;
                sIn[(c + 1) * 12 + nt] = tv.y;
                sIn[(c + 2) * 12 + nt] = tv.z;
                sIn[(c + 3) * 12 + nt] = tv.w;
            }
#pragma unroll
            for (int i = 0; i < 16; i++) acc16[i] = 0.f;
            if (v) {
                int beg = g_rowptr[n], end = g_rowptr[n + 1];
                for (int j = beg; j < end; j++) {
                    int s = g_srcs[j];
                    float w = wfp[j];
                    const float4* sr = (const float4*)(in_state + s * 64) + cg * 4;
#pragma unroll
                    for (int q = 0; q < 4; q++) {
                        float4 tv = sr[q];
                        acc16[q * 4 + 0] += w * tv.x;
                        acc16[q * 4 + 1] += w * tv.y;
                        acc16[q * 4 + 2] += w * tv.z;
                        acc16[q * 4 + 3] += w * tv.w;
                    }
                }
            }
#pragma unroll
            for (int i = 0; i < 16; i++) sA[(cg * 16 + i) * 12 + nt] = acc16[i];
        }
        __syncwarp();

        // ---- GraphConv: m = relu(agg@Wrel + brel + h@Wroot) ----
        {
            u64 am[4][2];
#pragma unroll
            for (int p = 0; p < 4; p++) { am[p][0] = 0ull; am[p][1] = 0ull; }
#pragma unroll 2
            for (int k = 0; k < 64; k++) {
                float4 w = ((const float4*)sWcv)[k * 32 + lane];
                u64 sr0 = splat2(w.x), sr1 = splat2(w.y);
                u64 so0 = splat2(w.z), so1 = splat2(w.w);
                u64 av[4], hvv[4];
                LOADU2(av, sA + k * 12);
                LOADU2(hvv, sIn + k * 12);
#pragma unroll
                for (int p = 0; p < 4; p++) {
                    am[p][0] = ffma2(av[p], sr0, am[p][0]);
                    am[p][0] = ffma2(hvv[p], so0, am[p][0]);
                    am[p][1] = ffma2(av[p], sr1, am[p][1]);
                    am[p][1] = ffma2(hvv[p], so1, am[p][1]);
                }
            }
            __syncwarp();   // done reading sA (agg) before overwrite with m
#pragma unroll
            for (int p = 0; p < 4; p++) {
                float2 c0 = unpk(am[p][0]), c1 = unpk(am[p][1]);
                float m00 = fmaxf(c0.x + br0, 0.f);
                float m10 = fmaxf(c0.y + br0, 0.f);
                float m01 = fmaxf(c1.x + br1, 0.f);
                float m11 = fmaxf(c1.y + br1, 0.f);
                *(u64*)(sA + d0 * 12 + 2 * p)       = pk(m00, m10);
                *(u64*)(sA + (d0 + 1) * 12 + 2 * p) = pk(m01, m11);
            }
        }
        __syncwarp();

        // ---- GRU pass 1: r and z gates ----
        u64 rp[8], zp[8];
        {
            u64 arz[4][4], hrz[4][4];
#pragma unroll
            for (int p = 0; p < 4; p++)
#pragma unroll
                for (int g = 0; g < 4; g++) { arz[p][g] = 0ull; hrz[p][g] = 0ull; }
#pragma unroll 2
            for (int k = 0; k < 64; k++) {
                float4 wi = ((const float4*)sWrzi)[k * 32 + lane];
                float4 wh = ((const float4*)sWrzh)[k * 32 + lane];
                u64 sir0 = splat2(wi.x), sir1 = splat2(wi.y);
                u64 siz0 = splat2(wi.z), siz1 = splat2(wi.w);
                u64 shr0 = splat2(wh.x), shr1 = splat2(wh.y);
                u64 shz0 = splat2(wh.z), shz1 = splat2(wh.w);
                u64 mv[4], hvv[4];
                LOADU2(mv, sA + k * 12);
                LOADU2(hvv, sIn + k * 12);
#pragma unroll
                for (int p = 0; p < 4; p++) {
                    arz[p][0] = ffma2(mv[p], sir0, arz[p][0]);
                    arz[p][1] = ffma2(mv[p], sir1, arz[p][1]);
                    arz[p][2] = ffma2(mv[p], siz0, arz[p][2]);
                    arz[p][3] = ffma2(mv[p], siz1, arz[p][3]);
                    hrz[p][0] = ffma2(hvv[p], shr0, hrz[p][0]);
                    hrz[p][1] = ffma2(hvv[p], shr1, hrz[p][1]);
                    hrz[p][2] = ffma2(hvv[p], shz0, hrz[p][2]);
                    hrz[p][3] = ffma2(hvv[p], shz1, hrz[p][3]);
                }
            }
#pragma unroll
            for (int p = 0; p < 4; p++) {
                float2 vir0 = unpk(arz[p][0]), vir1 = unpk(arz[p][1]);
                float2 viz0 = unpk(arz[p][2]), viz1 = unpk(arz[p][3]);
                float2 vhr0 = unpk(hrz[p][0]), vhr1 = unpk(hrz[p][1]);
                float2 vhz0 = unpk(hrz[p][2]), vhz1 = unpk(hrz[p][3]);
                float ra0 = sigm(vir0.x + bi_[0] + vhr0.x + bh_[0]);
                float rb0 = sigm(vir0.y + bi_[0] + vhr0.y + bh_[0]);
                float ra1 = sigm(vir1.x + bi_[1] + vhr1.x + bh_[1]);
                float rb1 = sigm(vir1.y + bi_[1] + vhr1.y + bh_[1]);
                float za0 = sigm(viz0.x + bi_[2] + vhz0.x + bh_[2]);
                float zb0 = sigm(viz0.y + bi_[2] + vhz0.y + bh_[2]);
                float za1 = sigm(viz1.x + bi_[3] + vhz1.x + bh_[3]);
                float zb1 = sigm(viz1.y + bi_[3] + vhz1.y + bh_[3]);
                rp[2 * p] = pk(ra0, rb0); rp[2 * p + 1] = pk(ra1, rb1);
                zp[2 * p] = pk(za0, zb0); zp[2 * p + 1] = pk(za1, zb1);
            }
        }

        // ---- GRU pass 2: n gate + blend + store ----
        {
            u64 an_[4][2], hn_[4][2];
#pragma unroll
            for (int p = 0; p < 4; p++) { an_[p][0] = 0ull; an_[p][1] = 0ull; hn_[p][0] = 0ull; hn_[p][1] = 0ull; }
#pragma unroll 2
            for (int k = 0; k < 64; k++) {
                float4 w = ((const float4*)sWn)[k * 32 + lane];
                u64 sin0 = splat2(w.x), sin1 = splat2(w.y);
                u64 shn0 = splat2(w.z), shn1 = splat2(w.w);
                u64 mv[4], hvv[4];
                LOADU2(mv, sA + k * 12);
                LOADU2(hvv, sIn + k * 12);
#pragma unroll
                for (int p = 0; p < 4; p++) {
                    an_[p][0] = ffma2(mv[p], sin0, an_[p][0]);
                    an_[p][1] = ffma2(mv[p], sin1, an_[p][1]);
                    hn_[p][0] = ffma2(hvv[p], shn0, hn_[p][0]);
                    hn_[p][1] = ffma2(hvv[p], shn1, hn_[p][1]);
                }
            }
#pragma unroll
            for (int p = 0; p < 4; p++) {
                float2 vin0 = unpk(an_[p][0]), vin1 = unpk(an_[p][1]);
                float2 vhn0 = unpk(hn_[p][0]), vhn1 = unpk(hn_[p][1]);
                float2 r0 = unpk(rp[2 * p]), r1 = unpk(rp[2 * p + 1]);
                float2 z0 = unpk(zp[2 * p]), z1 = unpk(zp[2 * p + 1]);
                float2 h0 = unpk(*(const u64*)(sIn + d0 * 12 + 2 * p));
                float2 h1 = unpk(*(const u64*)(sIn + (d0 + 1) * 12 + 2 * p));
                float na0 = tanh_f(vin0.x + bi_[4] + r0.x * (vhn0.x + bh_[4]));
                float nb0 = tanh_f(vin0.y + bi_[4] + r0.y * (vhn0.y + bh_[4]));
                float na1 = tanh_f(vin1.x + bi_[5] + r1.x * (vhn1.x + bh_[5]));
                float nb1 = tanh_f(vin1.y + bi_[5] + r1.y * (vhn1.y + bh_[5]));
                float oa0 = (1.f - z0.x) * na0 + z0.x * h0.x;
                float ob0 = (1.f - z0.y) * nb0 + z0.y * h0.y;
                float oa1 = (1.f - z1.x) * na1 + z1.x * h1.x;
                float ob1 = (1.f - z1.y) * nb1 + z1.y * h1.y;
                int na = n0 + 2 * p, nb = na + 1;
                if (na < Nn) *(float2*)(out_state + na * 64 + d0) = make_float2(oa0, oa1);
                if (nb < Nn) *(float2*)(out_state + nb * 64 + d0) = make_float2(ob0, ob1);
            }
        }
        __syncwarp();
    }
}

// ---------------- global mean pool ----------------
__global__ void k_pool(const float* __restrict__ feats, float* __restrict__ out) {
    int g = blockIdx.x, f = blockIdx.y, d = threadIdx.x;  // blockDim = 64
    int s = g_gstart[g], e = g_gstart[g + 1];
    const float* base = feats + f * Nn * Dd;
    float s0 = 0.f, s1 = 0.f, s2 = 0.f, s3 = 0.f;
    int i = s;
    for (; i + 3 < e; i += 4) {
        s0 += base[i * Dd + d];
        s1 += base[(i + 1) * Dd + d];
        s2 += base[(i + 2) * Dd + d];
        s3 += base[(i + 3) * Dd + d];
    }
    for (; i < e; i++) s0 += base[i * Dd + d];
    float sum = (s0 + s1) + (s2 + s3);
    int cnt = e - s;
    if (cnt < 1) cnt = 1;
    out[(f * Gg + g) * Dd + d] = sum / (float)cnt;
}

// ---------------- host ----------------
extern "C" void kernel_launch(void* const* d_in, const int* in_sizes, int n_in,
                              void* d_out, int out_size) {
    const float* x     = (const float*)d_in[0];
    const int*   ei    = (const int*)d_in[1];
    const float* att   = (const float*)d_in[2];
    const int*   batch = (const int*)d_in[3];
    const float* lin_W = (const float*)d_in[4];
    const float* lin_b = (const float*)d_in[5];
    const float* Wrel  = (const float*)d_in[6];
    const float* brel  = (const float*)d_in[7];
    const float* Wroot = (const float*)d_in[8];
    const float* Wih   = (const float*)d_in[9];
    const float* Whh   = (const float*)d_in[10];
    const float* bih   = (const float*)d_in[11];
    const float* bhh   = (const float*)d_in[12];

    float* out = (float*)d_out;
    float* feats = out + NFf * Gg * Dd;
    const int* srcp = ei;
    const int* dstp = ei + Ee;

    int sm = 148;
    cudaDeviceGetAttribute(&sm, cudaDevAttrMultiProcessorCount, 0);
    int grid = (sm / 4) * 4;
    if (grid < 4) grid = 4;

    cudaFuncSetAttribute(k_layer, cudaFuncAttributeMaxDynamicSharedMemorySize, LAYER_SHM);
    cudaFuncSetAttribute(k_lin, cudaFuncAttributeMaxDynamicSharedMemorySize, LIN_SHM);

    void *pa, *pb;
    cudaGetSymbolAddress(&pa, g_stateA);
    cudaGetSymbolAddress(&pb, g_stateB);
    float* A = (float*)pa;
    float* B = (float*)pb;

    const int NB = (Nn + 1023) / 1024;

    k_zero<<<(Nn + 255) / 256, 256>>>();
    k_hist<<<(Ee + 255) / 256, 256>>>(dstp, batch);
    k_scan1<<<NB, 1024>>>();
    k_scan2<<<1, 32>>>(NB);
    k_scan3<<<NB, 1024>>>();
    k_scatter<<<(Ee + 255) / 256, 256>>>(srcp, dstp);
    k_sortseg<<<(Nn + 127) / 128, 128>>>();
    k_buildw<<<(Ee + 255) / 256, 256>>>(att);
    k_gscan<<<1, 32>>>();
    k_pack<<<(24576 + 3 * 8192 + 255) / 256, 256>>>(Wrel, Wroot, Wih, Whh);

    k_lin<<<grid, 512, LIN_SHM>>>(x, lin_W, lin_b, A);
    k_layer<<<grid, 512, LAYER_SHM>>>(A, B, 0, brel, bih, bhh);
    k_layer<<<grid, 512, LAYER_SHM>>>(B, A, 1, brel, bih, bhh);
    k_layer<<<grid, 512, LAYER_SHM>>>(A, feats, 2, brel, bih, bhh);
    k_pool<<<dim3(Gg, NFf), 64>>>(feats, out);
}

// round 9
// speedup vs baseline: 1.0493x; 1.0493x over previous
#include <cuda_runtime.h>
#include <math.h>

typedef unsigned long long u64;
typedef unsigned int u32;

#define Nn 100000
#define Ee 1600000
#define Ff 128
#define NFf 4
#define Dd 64
#define NLl 3
#define Gg 128
#define NTILE 782   // ceil(Nn/128)

// ---------------- device scratch (no allocations allowed) ----------------
__device__ int   g_deg[Nn];
__device__ int   g_rowptr[Nn + 1];
__device__ int   g_fill[Nn];
__device__ int   g_bsums[256];
__device__ int   g_srcs[Ee];
__device__ int   g_eids[Ee];
__device__ float g_wcsr[NFf * Ee];
__device__ float g_stateA[NFf * Nn * Dd];
__device__ float g_stateB[NFf * Nn * Dd];
__device__ int   g_gcnt[Gg];
__device__ int   g_gstart[Gg + 1];
__device__ float g_packcv[NFf * NLl * 8192];   // [wl][k][lane] f4: wrel0,wrel1,wroot0,wroot1
__device__ float g_packrzi[NFf * 8192];        // [f][k][lane] f4: wih_r0,wih_r1,wih_z0,wih_z1
__device__ float g_packrzh[NFf * 8192];        // [f][k][lane] f4: whh_r0,whh_r1,whh_z0,whh_z1
__device__ float g_packn[NFf * 8192];          // [f][k][lane] f4: wih_n0,wih_n1,whh_n0,whh_n1

// ---------------- packed f32x2 helpers ----------------
__device__ __forceinline__ u64 ffma2(u64 a, u64 b, u64 c) {
    u64 d; asm("fma.rn.f32x2 %0,%1,%2,%3;" : "=l"(d) : "l"(a), "l"(b), "l"(c)); return d;
}
__device__ __forceinline__ u64 splat2(float v) {
    u64 d; u32 r = __float_as_uint(v);
    asm("mov.b64 %0,{%1,%2};" : "=l"(d) : "r"(r), "r"(r)); return d;
}
__device__ __forceinline__ float2 unpk(u64 v) {
    u32 lo, hi; asm("mov.b64 {%0,%1},%2;" : "=r"(lo), "=r"(hi) : "l"(v));
    return make_float2(__uint_as_float(lo), __uint_as_float(hi));
}
__device__ __forceinline__ u64 pk(float a, float b) {
    u64 d;
    asm("mov.b64 %0,{%1,%2};" : "=l"(d) : "r"(__float_as_uint(a)), "r"(__float_as_uint(b)));
    return d;
}
__device__ __forceinline__ float sigm(float v) { return 1.f / (1.f + __expf(-v)); }
__device__ __forceinline__ float tanh_f(float v) { return 2.f / (1.f + __expf(-2.f * v)) - 1.f; }

// load 4 node-pairs (32B) via 2 LDS.128 broadcasts
#define LOADP4(dst, base) do { \
    const float4* _p4 = (const float4*)(base); \
    float4 _a = _p4[0], _b = _p4[1]; \
    dst[0] = pk(_a.x, _a.y); dst[1] = pk(_a.z, _a.w); \
    dst[2] = pk(_b.x, _b.y); dst[3] = pk(_b.z, _b.w); \
} while (0)

// ---------------- CSR build ----------------
__global__ void k_zero() {
    int i = blockIdx.x * blockDim.x + threadIdx.x;
    if (i < Nn) g_deg[i] = 0;
    if (i < Gg) g_gcnt[i] = 0;
}

__global__ void k_hist(const int* __restrict__ dst, const int* __restrict__ batch) {
    int i = blockIdx.x * blockDim.x + threadIdx.x;
    if (i < Ee) atomicAdd(&g_deg[dst[i]], 1);
    if (i < Nn) atomicAdd(&g_gcnt[batch[i]], 1);
}

__global__ void k_scan1() {
    __shared__ int tmp[1024];
    int i = blockIdx.x * 1024 + threadIdx.x;
    int v = (i < Nn) ? g_deg[i] : 0;
    tmp[threadIdx.x] = v;
    __syncthreads();
    for (int off = 1; off < 1024; off <<= 1) {
        int t = 0;
        if (threadIdx.x >= off) t = tmp[threadIdx.x - off];
        __syncthreads();
        if (threadIdx.x >= off) tmp[threadIdx.x] += t;
        __syncthreads();
    }
    if (i < Nn) g_rowptr[i + 1] = tmp[threadIdx.x];
    if (threadIdx.x == 1023) g_bsums[blockIdx.x] = tmp[1023];
}

__global__ void k_scan2(int nb) {
    if (threadIdx.x == 0 && blockIdx.x == 0) {
        int run = 0;
        for (int b = 0; b < nb; b++) { int v = g_bsums[b]; g_bsums[b] = run; run += v; }
    }
}

__global__ void k_scan3() {
    int i = blockIdx.x * 1024 + threadIdx.x;
    if (i < Nn) {
        int v = g_rowptr[i + 1] + g_bsums[blockIdx.x];
        g_rowptr[i + 1] = v;
        if (i + 1 < Nn) g_fill[i + 1] = v;
    }
    if (i == 0) { g_rowptr[0] = 0; g_fill[0] = 0; }
}

__global__ void k_scatter(const int* __restrict__ src, const int* __restrict__ dst) {
    int e = blockIdx.x * blockDim.x + threadIdx.x;
    if (e < Ee) {
        int d = dst[e];
        int p = atomicAdd(&g_fill[d], 1);
        g_srcs[p] = src[e];
        g_eids[p] = e;
    }
}

__global__ void k_sortseg() {
    int n = blockIdx.x * blockDim.x + threadIdx.x;
    if (n >= Nn) return;
    int b = g_rowptr[n], e = g_rowptr[n + 1];
    for (int i = b + 1; i < e; i++) {
        int ke = g_eids[i], ks = g_srcs[i];
        int j = i - 1;
        while (j >= b && g_eids[j] > ke) {
            g_eids[j + 1] = g_eids[j];
            g_srcs[j + 1] = g_srcs[j];
            j--;
        }
        g_eids[j + 1] = ke;
        g_srcs[j + 1] = ks;
    }
}

__global__ void k_buildw(const float* __restrict__ att) {
    int j = blockIdx.x * blockDim.x + threadIdx.x;
    if (j < Ee) {
        int e = g_eids[j];
#pragma unroll
        for (int f = 0; f < NFf; f++) g_wcsr[f * Ee + j] = att[f * Ee + e];
    }
}

__global__ void k_gscan() {
    if (threadIdx.x == 0 && blockIdx.x == 0) {
        int run = 0;
        for (int g = 0; g < Gg; g++) { g_gstart[g] = run; run += g_gcnt[g]; }
        g_gstart[Gg] = run;
    }
}

// ---------------- weight pre-pack ----------------
__global__ void k_pack(const float* __restrict__ Wrel, const float* __restrict__ Wroot,
                       const float* __restrict__ Wih, const float* __restrict__ Whh) {
    int i = blockIdx.x * blockDim.x + threadIdx.x;
    if (i < 24576) {           // conv: 12 layers x 2048
        int wl = i >> 11, r = i & 2047, k = r >> 5, l = r & 31;
        const float* A = Wrel + wl * 4096;
        const float* B = Wroot + wl * 4096;
        ((float4*)g_packcv)[i] = make_float4(A[k * 64 + 2 * l], A[k * 64 + 2 * l + 1],
                                             B[k * 64 + 2 * l], B[k * 64 + 2 * l + 1]);
        return;
    }
    int j = i - 24576;
    if (j < 8192) {            // rz input weights
        int f = j >> 11, r = j & 2047, k = r >> 5, l = r & 31;
        const float* I = Wih + f * 12288;
        ((float4*)g_packrzi)[j] = make_float4(I[(2 * l) * 64 + k], I[(2 * l + 1) * 64 + k],
                                              I[(64 + 2 * l) * 64 + k], I[(64 + 2 * l + 1) * 64 + k]);
        return;
    }
    j -= 8192;
    if (j < 8192) {            // rz hidden weights
        int f = j >> 11, r = j & 2047, k = r >> 5, l = r & 31;
        const float* H = Whh + f * 12288;
        ((float4*)g_packrzh)[j] = make_float4(H[(2 * l) * 64 + k], H[(2 * l + 1) * 64 + k],
                                              H[(64 + 2 * l) * 64 + k], H[(64 + 2 * l + 1) * 64 + k]);
        return;
    }
    j -= 8192;
    if (j < 8192) {            // n gate weights (ih + hh)
        int f = j >> 11, r = j & 2047, k = r >> 5, l = r & 31;
        const float* I = Wih + f * 12288;
        const float* H = Whh + f * 12288;
        ((float4*)g_packn)[j] = make_float4(I[(128 + 2 * l) * 64 + k], I[(128 + 2 * l + 1) * 64 + k],
                                            H[(128 + 2 * l) * 64 + k], H[(128 + 2 * l + 1) * 64 + k]);
    }
}

// ---------------- lin (all factors, 8 nodes/warp, 16 warps) ----------------
#define LIN_SHM ((8192 + 64 + 16 * 1280) * 4)
__global__ __launch_bounds__(512, 1) void k_lin(const float* __restrict__ x,
                                                const float* __restrict__ W_all,
                                                const float* __restrict__ b_all,
                                                float* __restrict__ out_base) {
    extern __shared__ float sh[];
    float* sW = sh;
    float* sb = sW + 8192;
    float* sX = sb + 64;
    int f = blockIdx.x & 3;
    int fslot = blockIdx.x >> 2;
    int nslot = gridDim.x >> 2;
    const float* W = W_all + f * Ff * Dd;
    const float* b = b_all + f * Dd;
    float* out = out_base + f * Nn * Dd;

    int tid = threadIdx.x;
    for (int i = tid; i < 8192; i += 512) sW[i] = W[i];
    if (tid < 64) sb[tid] = b[tid];
    __syncthreads();
    int warp = tid >> 5, lane = tid & 31;
    int d0 = 2 * lane;
    int nt = lane >> 2, cg = lane & 3;
    float* sXw = sX + warp * 1280;
    float bc0 = sb[d0], bc1 = sb[d0 + 1];

    for (int t = fslot; t < NTILE; t += nslot) {
        int n0 = t * 128 + warp * 8;
        if (n0 >= Nn) continue;
        {
            int n = n0 + nt;
            bool v = n < Nn;
            const float4* xr = (const float4*)(x + (v ? n : 0) * Ff) + cg * 8;
#pragma unroll
            for (int q = 0; q < 8; q++) {
                float4 tv = v ? xr[q] : make_float4(0, 0, 0, 0);
                int c = cg * 32 + q * 4;
                sXw[(c + 0) * 10 + nt] = tv.x;
                sXw[(c + 1) * 10 + nt] = tv.y;
                sXw[(c + 2) * 10 + nt] = tv.z;
                sXw[(c + 3) * 10 + nt] = tv.w;
            }
        }
        __syncwarp();
        u64 acc[4][2];
#pragma unroll
        for (int p = 0; p < 4; p++) { acc[p][0] = 0ull; acc[p][1] = 0ull; }
#pragma unroll 4
        for (int k = 0; k < Ff; k++) {
            float2 w = *(const float2*)(sW + k * 64 + d0);
            u64 sw0 = splat2(w.x), sw1 = splat2(w.y);
            const u64* xp = (const u64*)(sXw + k * 10);
#pragma unroll
            for (int p = 0; p < 4; p++) {
                u64 xv = xp[p];
                acc[p][0] = ffma2(xv, sw0, acc[p][0]);
                acc[p][1] = ffma2(xv, sw1, acc[p][1]);
            }
        }
#pragma unroll
        for (int p = 0; p < 4; p++) {
            float2 a0 = unpk(acc[p][0]), a1 = unpk(acc[p][1]);
            int na = n0 + 2 * p, nb = na + 1;
            if (na < Nn) *(float2*)(out + na * 64 + d0) = make_float2(a0.x + bc0, a1.x + bc1);
            if (nb < Nn) *(float2*)(out + nb * 64 + d0) = make_float2(a0.y + bc0, a1.y + bc1);
        }
        __syncwarp();
    }
}

// ---------------- fused layer (all factors, 8 nodes/warp, 16 warps) ----------------
// stage stride 12 floats (48B, 16B-aligned) so acts load as LDS.128
#define LAYER_SHM ((8192 * 4 + 16 * 1536) * 4)
__global__ __launch_bounds__(512, 1) void k_layer(const float* __restrict__ in_base,
                                                  float* __restrict__ out_base,
                                                  int layer,
                                                  const float* __restrict__ brel_all,
                                                  const float* __restrict__ bih_all,
                                                  const float* __restrict__ bhh_all) {
    extern __shared__ float sh[];
    float* sWcv  = sh;               // 8192: [k][lane] f4
    float* sWrzi = sWcv + 8192;      // 8192
    float* sWrzh = sWrzi + 8192;     // 8192
    float* sWn   = sWrzh + 8192;     // 8192
    float* sStage = sWn + 8192;      // 16 warps * 1536

    int f = blockIdx.x & 3;
    int fslot = blockIdx.x >> 2;
    int nslot = gridDim.x >> 2;
    int wl = f * NLl + layer;
    const float* in_state = in_base + f * Nn * Dd;
    float* out_state = out_base + f * Nn * Dd;
    const float* wfp = g_wcsr + f * Ee;

    int tid = threadIdx.x;
    {
        const float4* p0 = (const float4*)(g_packcv + wl * 8192);
        const float4* p1 = (const float4*)(g_packrzi + f * 8192);
        const float4* p2 = (const float4*)(g_packrzh + f * 8192);
        const float4* p3 = (const float4*)(g_packn + f * 8192);
        float4* d0_ = (float4*)sWcv;
        float4* d1_ = (float4*)sWrzi;
        float4* d2_ = (float4*)sWrzh;
        float4* d3_ = (float4*)sWn;
        for (int i = tid; i < 2048; i += 512) {
            d0_[i] = p0[i]; d1_[i] = p1[i]; d2_[i] = p2[i]; d3_[i] = p3[i];
        }
    }
    __syncthreads();

    int warp = tid >> 5, lane = tid & 31;
    int d0 = 2 * lane;
    int nt = lane >> 2, cg = lane & 3;
    float* sIn = sStage + warp * 1536;   // [col][12]
    float* sA  = sIn + 768;              // agg, then m

    const float* brel = brel_all + wl * 64;
    float br0 = brel[d0], br1 = brel[d0 + 1];
    float bi_[6], bh_[6];
#pragma unroll
    for (int g = 0; g < 3; g++) {
        bi_[2 * g] = bih_all[f * 192 + 64 * g + d0];
        bi_[2 * g + 1] = bih_all[f * 192 + 64 * g + d0 + 1];
        bh_[2 * g] = bhh_all[f * 192 + 64 * g + d0];
        bh_[2 * g + 1] = bhh_all[f * 192 + 64 * g + d0 + 1];
    }

    for (int t = fslot; t < NTILE; t += nslot) {
        int n0 = t * 128 + warp * 8;
        if (n0 >= Nn) continue;

        // ---- stage h + edge aggregation (unroll-2, MLP 8), transposed [col][node] ----
        {
            int n = n0 + nt;
            bool v = n < Nn;
            const float4* xr = (const float4*)(in_state + (v ? n : 0) * 64) + cg * 4;
            float acc16[16];
#pragma unroll
            for (int q = 0; q < 4; q++) {
                float4 tv = v ? xr[q] : make_float4(0, 0, 0, 0);
                int c = cg * 16 + q * 4;
                sIn[(c + 0) * 12 + nt] = tv.x;
                sIn[(c + 1) * 12 + nt] = tv.y;
                sIn[(c + 2) * 12 + nt] = tv.z;
                sIn[(c + 3) * 12 + nt] = tv.w;
            }
#pragma unroll
            for (int i = 0; i < 16; i++) acc16[i] = 0.f;
            if (v) {
                int beg = g_rowptr[n], end = g_rowptr[n + 1];
                int j = beg;
                for (; j + 2 <= end; j += 2) {
                    int s0 = g_srcs[j], s1 = g_srcs[j + 1];
                    float w0 = wfp[j], w1 = wfp[j + 1];
                    const float4* r0p = (const float4*)(in_state + s0 * 64) + cg * 4;
                    const float4* r1p = (const float4*)(in_state + s1 * 64) + cg * 4;
                    float4 a0 = r0p[0], a1 = r0p[1], a2 = r0p[2], a3 = r0p[3];
                    float4 b0 = r1p[0], b1 = r1p[1], b2 = r1p[2], b3 = r1p[3];
                    // edge j first (original order), then edge j+1
                    acc16[0]  += w0 * a0.x; acc16[1]  += w0 * a0.y; acc16[2]  += w0 * a0.z; acc16[3]  += w0 * a0.w;
                    acc16[4]  += w0 * a1.x; acc16[5]  += w0 * a1.y; acc16[6]  += w0 * a1.z; acc16[7]  += w0 * a1.w;
                    acc16[8]  += w0 * a2.x; acc16[9]  += w0 * a2.y; acc16[10] += w0 * a2.z; acc16[11] += w0 * a2.w;
                    acc16[12] += w0 * a3.x; acc16[13] += w0 * a3.y; acc16[14] += w0 * a3.z; acc16[15] += w0 * a3.w;
                    acc16[0]  += w1 * b0.x; acc16[1]  += w1 * b0.y; acc16[2]  += w1 * b0.z; acc16[3]  += w1 * b0.w;
                    acc16[4]  += w1 * b1.x; acc16[5]  += w1 * b1.y; acc16[6]  += w1 * b1.z; acc16[7]  += w1 * b1.w;
                    acc16[8]  += w1 * b2.x; acc16[9]  += w1 * b2.y; acc16[10] += w1 * b2.z; acc16[11] += w1 * b2.w;
                    acc16[12] += w1 * b3.x; acc16[13] += w1 * b3.y; acc16[14] += w1 * b3.z; acc16[15] += w1 * b3.w;
                }
                if (j < end) {
                    int s = g_srcs[j];
                    float w = wfp[j];
                    const float4* sr = (const float4*)(in_state + s * 64) + cg * 4;
#pragma unroll
                    for (int q = 0; q < 4; q++) {
                        float4 tv = sr[q];
                        acc16[q * 4 + 0] += w * tv.x;
                        acc16[q * 4 + 1] += w * tv.y;
                        acc16[q * 4 + 2] += w * tv.z;
                        acc16[q * 4 + 3] += w * tv.w;
                    }
                }
            }
#pragma unroll
            for (int i = 0; i < 16; i++) sA[(cg * 16 + i) * 12 + nt] = acc16[i];
        }
        __syncwarp();

        // ---- GraphConv: m = relu(agg@Wrel + brel + h@Wroot) ----
        {
            u64 am[4][2];
#pragma unroll
            for (int p = 0; p < 4; p++) { am[p][0] = 0ull; am[p][1] = 0ull; }
#pragma unroll 2
            for (int k = 0; k < 64; k++) {
                float4 w = ((const float4*)sWcv)[k * 32 + lane];
                u64 sr0 = splat2(w.x), sr1 = splat2(w.y);
                u64 so0 = splat2(w.z), so1 = splat2(w.w);
                u64 av[4], hvv[4];
                LOADP4(av, sA + k * 12);
                LOADP4(hvv, sIn + k * 12);
#pragma unroll
                for (int p = 0; p < 4; p++) {
                    am[p][0] = ffma2(av[p], sr0, am[p][0]);
                    am[p][0] = ffma2(hvv[p], so0, am[p][0]);
                    am[p][1] = ffma2(av[p], sr1, am[p][1]);
                    am[p][1] = ffma2(hvv[p], so1, am[p][1]);
                }
            }
            __syncwarp();   // done reading sA (agg) before overwrite with m
#pragma unroll
            for (int p = 0; p < 4; p++) {
                float2 c0 = unpk(am[p][0]), c1 = unpk(am[p][1]);
                float m00 = fmaxf(c0.x + br0, 0.f);
                float m10 = fmaxf(c0.y + br0, 0.f);
                float m01 = fmaxf(c1.x + br1, 0.f);
                float m11 = fmaxf(c1.y + br1, 0.f);
                *(u64*)(sA + d0 * 12 + 2 * p)       = pk(m00, m10);
                *(u64*)(sA + (d0 + 1) * 12 + 2 * p) = pk(m01, m11);
            }
        }
        __syncwarp();

        // ---- GRU pass 1: r and z gates ----
        u64 rp[8], zp[8];
        {
            u64 arz[4][4], hrz[4][4];
#pragma unroll
            for (int p = 0; p < 4; p++)
#pragma unroll
                for (int g = 0; g < 4; g++) { arz[p][g] = 0ull; hrz[p][g] = 0ull; }
#pragma unroll 1
            for (int k = 0; k < 64; k++) {
                float4 wi = ((const float4*)sWrzi)[k * 32 + lane];
                float4 wh = ((const float4*)sWrzh)[k * 32 + lane];
                u64 sir0 = splat2(wi.x), sir1 = splat2(wi.y);
                u64 siz0 = splat2(wi.z), siz1 = splat2(wi.w);
                u64 shr0 = splat2(wh.x), shr1 = splat2(wh.y);
                u64 shz0 = splat2(wh.z), shz1 = splat2(wh.w);
                u64 mv[4], hvv[4];
                LOADP4(mv, sA + k * 12);
                LOADP4(hvv, sIn + k * 12);
#pragma unroll
                for (int p = 0; p < 4; p++) {
                    arz[p][0] = ffma2(mv[p], sir0, arz[p][0]);
                    arz[p][1] = ffma2(mv[p], sir1, arz[p][1]);
                    arz[p][2] = ffma2(mv[p], siz0, arz[p][2]);
                    arz[p][3] = ffma2(mv[p], siz1, arz[p][3]);
                    hrz[p][0] = ffma2(hvv[p], shr0, hrz[p][0]);
                    hrz[p][1] = ffma2(hvv[p], shr1, hrz[p][1]);
                    hrz[p][2] = ffma2(hvv[p], shz0, hrz[p][2]);
                    hrz[p][3] = ffma2(hvv[p], shz1, hrz[p][3]);
                }
            }
#pragma unroll
            for (int p = 0; p < 4; p++) {
                float2 vir0 = unpk(arz[p][0]), vir1 = unpk(arz[p][1]);
                float2 viz0 = unpk(arz[p][2]), viz1 = unpk(arz[p][3]);
                float2 vhr0 = unpk(hrz[p][0]), vhr1 = unpk(hrz[p][1]);
                float2 vhz0 = unpk(hrz[p][2]), vhz1 = unpk(hrz[p][3]);
                float ra0 = sigm(vir0.x + bi_[0] + vhr0.x + bh_[0]);
                float rb0 = sigm(vir0.y + bi_[0] + vhr0.y + bh_[0]);
                float ra1 = sigm(vir1.x + bi_[1] + vhr1.x + bh_[1]);
                float rb1 = sigm(vir1.y + bi_[1] + vhr1.y + bh_[1]);
                float za0 = sigm(viz0.x + bi_[2] + vhz0.x + bh_[2]);
                float zb0 = sigm(viz0.y + bi_[2] + vhz0.y + bh_[2]);
                float za1 = sigm(viz1.x + bi_[3] + vhz1.x + bh_[3]);
                float zb1 = sigm(viz1.y + bi_[3] + vhz1.y + bh_[3]);
                rp[2 * p] = pk(ra0, rb0); rp[2 * p + 1] = pk(ra1, rb1);
                zp[2 * p] = pk(za0, zb0); zp[2 * p + 1] = pk(za1, zb1);
            }
        }

        // ---- GRU pass 2: n gate + blend + store ----
        {
            u64 an_[4][2], hn_[4][2];
#pragma unroll
            for (int p = 0; p < 4; p++) { an_[p][0] = 0ull; an_[p][1] = 0ull; hn_[p][0] = 0ull; hn_[p][1] = 0ull; }
#pragma unroll 2
            for (int k = 0; k < 64; k++) {
                float4 w = ((const float4*)sWn)[k * 32 + lane];
                u64 sin0 = splat2(w.x), sin1 = splat2(w.y);
                u64 shn0 = splat2(w.z), shn1 = splat2(w.w);
                u64 mv[4], hvv[4];
                LOADP4(mv, sA + k * 12);
                LOADP4(hvv, sIn + k * 12);
#pragma unroll
                for (int p = 0; p < 4; p++) {
                    an_[p][0] = ffma2(mv[p], sin0, an_[p][0]);
                    an_[p][1] = ffma2(mv[p], sin1, an_[p][1]);
                    hn_[p][0] = ffma2(hvv[p], shn0, hn_[p][0]);
                    hn_[p][1] = ffma2(hvv[p], shn1, hn_[p][1]);
                }
            }
#pragma unroll
            for (int p = 0; p < 4; p++) {
                float2 vin0 = unpk(an_[p][0]), vin1 = unpk(an_[p][1]);
                float2 vhn0 = unpk(hn_[p][0]), vhn1 = unpk(hn_[p][1]);
                float2 r0 = unpk(rp[2 * p]), r1 = unpk(rp[2 * p + 1]);
                float2 z0 = unpk(zp[2 * p]), z1 = unpk(zp[2 * p + 1]);
                float2 h0 = unpk(*(const u64*)(sIn + d0 * 12 + 2 * p));
                float2 h1 = unpk(*(const u64*)(sIn + (d0 + 1) * 12 + 2 * p));
                float na0 = tanh_f(vin0.x + bi_[4] + r0.x * (vhn0.x + bh_[4]));
                float nb0 = tanh_f(vin0.y + bi_[4] + r0.y * (vhn0.y + bh_[4]));
                float na1 = tanh_f(vin1.x + bi_[5] + r1.x * (vhn1.x + bh_[5]));
                float nb1 = tanh_f(vin1.y + bi_[5] + r1.y * (vhn1.y + bh_[5]));
                float oa0 = (1.f - z0.x) * na0 + z0.x * h0.x;
                float ob0 = (1.f - z0.y) * nb0 + z0.y * h0.y;
                float oa1 = (1.f - z1.x) * na1 + z1.x * h1.x;
                float ob1 = (1.f - z1.y) * nb1 + z1.y * h1.y;
                int na = n0 + 2 * p, nb = na + 1;
                if (na < Nn) *(float2*)(out_state + na * 64 + d0) = make_float2(oa0, oa1);
                if (nb < Nn) *(float2*)(out_state + nb * 64 + d0) = make_float2(ob0, ob1);
            }
        }
        __syncwarp();
    }
}

// ---------------- global mean pool ----------------
__global__ void k_pool(const float* __restrict__ feats, float* __restrict__ out) {
    int g = blockIdx.x, f = blockIdx.y, d = threadIdx.x;  // blockDim = 64
    int s = g_gstart[g], e = g_gstart[g + 1];
    const float* base = feats + f * Nn * Dd;
    float s0 = 0.f, s1 = 0.f, s2 = 0.f, s3 = 0.f;
    int i = s;
    for (; i + 3 < e; i += 4) {
        s0 += base[i * Dd + d];
        s1 += base[(i + 1) * Dd + d];
        s2 += base[(i + 2) * Dd + d];
        s3 += base[(i + 3) * Dd + d];
    }
    for (; i < e; i++) s0 += base[i * Dd + d];
    float sum = (s0 + s1) + (s2 + s3);
    int cnt = e - s;
    if (cnt < 1) cnt = 1;
    out[(f * Gg + g) * Dd + d] = sum / (float)cnt;
}

// ---------------- host ----------------
extern "C" void kernel_launch(void* const* d_in, const int* in_sizes, int n_in,
                              void* d_out, int out_size) {
    const float* x     = (const float*)d_in[0];
    const int*   ei    = (const int*)d_in[1];
    const float* att   = (const float*)d_in[2];
    const int*   batch = (const int*)d_in[3];
    const float* lin_W = (const float*)d_in[4];
    const float* lin_b = (const float*)d_in[5];
    const float* Wrel  = (const float*)d_in[6];
    const float* brel  = (const float*)d_in[7];
    const float* Wroot = (const float*)d_in[8];
    const float* Wih   = (const float*)d_in[9];
    const float* Whh   = (const float*)d_in[10];
    const float* bih   = (const float*)d_in[11];
    const float* bhh   = (const float*)d_in[12];

    float* out = (float*)d_out;
    float* feats = out + NFf * Gg * Dd;
    const int* srcp = ei;
    const int* dstp = ei + Ee;

    int sm = 148;
    cudaDeviceGetAttribute(&sm, cudaDevAttrMultiProcessorCount, 0);
    int grid = (sm / 4) * 4;
    if (grid < 4) grid = 4;

    cudaFuncSetAttribute(k_layer, cudaFuncAttributeMaxDynamicSharedMemorySize, LAYER_SHM);
    cudaFuncSetAttribute(k_lin, cudaFuncAttributeMaxDynamicSharedMemorySize, LIN_SHM);

    void *pa, *pb;
    cudaGetSymbolAddress(&pa, g_stateA);
    cudaGetSymbolAddress(&pb, g_stateB);
    float* A = (float*)pa;
    float* B = (float*)pb;

    const int NB = (Nn + 1023) / 1024;

    k_zero<<<(Nn + 255) / 256, 256>>>();
    k_hist<<<(Ee + 255) / 256, 256>>>(dstp, batch);
    k_scan1<<<NB, 1024>>>();
    k_scan2<<<1, 32>>>(NB);
    k_scan3<<<NB, 1024>>>();
    k_scatter<<<(Ee + 255) / 256, 256>>>(srcp, dstp);
    k_sortseg<<<(Nn + 127) / 128, 128>>>();
    k_buildw<<<(Ee + 255) / 256, 256>>>(att);
    k_gscan<<<1, 32>>>();
    k_pack<<<(24576 + 3 * 8192 + 255) / 256, 256>>>(Wrel, Wroot, Wih, Whh);

    k_lin<<<grid, 512, LIN_SHM>>>(x, lin_W, lin_b, A);
    k_layer<<<grid, 512, LAYER_SHM>>>(A, B, 0, brel, bih, bhh);
    k_layer<<<grid, 512, LAYER_SHM>>>(B, A, 1, brel, bih, bhh);
    k_layer<<<grid, 512, LAYER_SHM>>>(A, feats, 2, brel, bih, bhh);
    k_pool<<<dim3(Gg, NFf), 64>>>(feats, out);
}